// round 12
// baseline (speedup 1.0000x reference)
#include <cuda_runtime.h>
#include <cuda_bf16.h>
#include <cuda_fp16.h>
#include <cstdint>
#include <cstddef>

// Problem constants
#define BATCH   4096
#define DIM     512
#define QSIZE   32768
#define NHARD   9830
#define NRAND   22938
#define INV_T   (1.0f/0.07f)
#define KEXP    (INV_T * 1.44269504f)   // log2(e)/T

// -------- device scratch (static allocation; no cudaMalloc allowed) --------
__device__ __half  g_eegn[BATCH * DIM];            // 4 MB  normalized eeg, fp16
__device__ __half  g_qbf[QSIZE * DIM];             // 32 MB queue, fp16
__device__ __half  g_neg[(size_t)BATCH * QSIZE];   // 256 MB
__device__ float   g_pos[BATCH];
__device__ double  g_sums[2];

// ---------------------------------------------------------------------------
__global__ void k_zero() { g_sums[0] = 0.0; g_sums[1] = 0.0; }

__global__ __launch_bounds__(128) void k_norm(const float* __restrict__ eeg,
                                              const float* __restrict__ clip) {
    int b = blockIdx.x, t = threadIdx.x;
    float4 e = ((const float4*)(eeg  + (size_t)b * DIM))[t];
    float4 c = ((const float4*)(clip + (size_t)b * DIM))[t];
    float se = e.x*e.x + e.y*e.y + e.z*e.z + e.w*e.w;
    float sc = c.x*c.x + c.y*c.y + c.z*c.z + c.w*c.w;
    float sd = e.x*c.x + e.y*c.y + e.z*c.z + e.w*c.w;
    #pragma unroll
    for (int o = 16; o; o >>= 1) {
        se += __shfl_down_sync(0xFFFFFFFFu, se, o);
        sc += __shfl_down_sync(0xFFFFFFFFu, sc, o);
        sd += __shfl_down_sync(0xFFFFFFFFu, sd, o);
    }
    __shared__ float rs[3][4];
    __shared__ float sInvE;
    int w = t >> 5, l = t & 31;
    if (l == 0) { rs[0][w] = se; rs[1][w] = sc; rs[2][w] = sd; }
    __syncthreads();
    if (t == 0) {
        float SE = rs[0][0] + rs[0][1] + rs[0][2] + rs[0][3];
        float SC = rs[1][0] + rs[1][1] + rs[1][2] + rs[1][3];
        float SD = rs[2][0] + rs[2][1] + rs[2][2] + rs[2][3];
        float ie = 1.0f / fmaxf(sqrtf(SE), 1e-12f);
        float ic = 1.0f / fmaxf(sqrtf(SC), 1e-12f);
        sInvE = ie;
        g_pos[b] = SD * ie * ic;
    }
    __syncthreads();
    float ie = sInvE;
    __half* dst = g_eegn + (size_t)b * DIM + t * 4;
    dst[0] = __float2half(e.x * ie);
    dst[1] = __float2half(e.y * ie);
    dst[2] = __float2half(e.z * ie);
    dst[3] = __float2half(e.w * ie);
}

__global__ __launch_bounds__(256) void k_convq(const float* __restrict__ q) {
    int i = blockIdx.x * 256 + threadIdx.x;
    float4 v = ((const float4*)q)[i];
    __half2* d = (__half2*)g_qbf;
    d[2 * i]     = __floats2half2_rn(v.x, v.y);
    d[2 * i + 1] = __floats2half2_rn(v.z, v.w);
}

// ---------------------------------------------------------------------------
// mma.sync fp16 GEMM, f16 accumulate. (round-10 best config, unchanged)
// CTA tile 128x256, 256 threads, warp grid 2x4, warp tile 64x64.
// 3-stage cp.async, 92KB smem -> 2 CTAs/SM.
// ---------------------------------------------------------------------------
__device__ __forceinline__ uint32_t smem_u32(const void* p) {
    return (uint32_t)__cvta_generic_to_shared(p);
}
__device__ __forceinline__ void cp16(uint32_t s, const void* g) {
    asm volatile("cp.async.cg.shared.global [%0], [%1], 16;\n" :: "r"(s), "l"(g));
}
__device__ __forceinline__ void cp_commit() { asm volatile("cp.async.commit_group;\n"); }
template <int N> __device__ __forceinline__ void cp_wait() {
    asm volatile("cp.async.wait_group %0;\n" :: "n"(N));
}

#define LDSK 40                        // 32 + 8 pad elems: 80B rows
#define STAGES 3
#define KTILES 16                      // DIM / 32
#define A_STAGE_B (128 * LDSK * 2)     // 10240 B
#define B_STAGE_B (256 * LDSK * 2)     // 20480 B
#define STAGE_B   (A_STAGE_B + B_STAGE_B)
#define GEMM_SMEM (STAGES * STAGE_B)   // 92160 B -> 2 CTAs/SM

__global__ __launch_bounds__(256, 2) void k_gemm() {
    extern __shared__ __align__(16) unsigned char smraw[];
    uint32_t sbase = smem_u32(smraw);
    int tid = threadIdx.x, warp = tid >> 5, lane = tid & 31;
    int bn = blockIdx.x, bm = blockIdx.y;
    int wm = warp & 1, wn = warp >> 1;   // 2(m) x 4(n); warp tile 64x64

    const __half* Abase = g_eegn + (size_t)bm * 128 * DIM;
    const __half* Bbase = g_qbf  + (size_t)bn * 256 * DIM;

    auto load_stage = [&](int s, int kt) {
        uint32_t sa = sbase + s * STAGE_B;
        uint32_t sb = sa + A_STAGE_B;
        #pragma unroll
        for (int i = 0; i < 6; ++i) {               // 1536 16B chunks / 256 thr
            int c = tid + i * 256;
            uint32_t dst; const __half* g; int row, col;
            if (c < 512) { row = c >> 2; col = c & 3; dst = sa;
                           g = Abase + (size_t)row * DIM + kt * 32 + col * 8; }
            else { int cb = c - 512; row = cb >> 2; col = cb & 3; dst = sb;
                   g = Bbase + (size_t)row * DIM + kt * 32 + col * 8; }
            cp16(dst + (uint32_t)(row * (LDSK * 2) + col * 16), g);
        }
    };

    uint32_t acc[4][8][2];               // f16x2 accumulators
    #pragma unroll
    for (int i = 0; i < 4; i++)
        #pragma unroll
        for (int j = 0; j < 8; j++) { acc[i][j][0] = 0u; acc[i][j][1] = 0u; }

    int aRow = wm * 64 + (lane & 15);
    int aK0  = (lane >> 4) * 8;
    int bRow = wn * 64 + (lane & 7) + ((lane & 16) >> 1);
    int bK0  = ((lane >> 3) & 1) * 8;

    #pragma unroll
    for (int s = 0; s < STAGES - 1; ++s) { load_stage(s, s); cp_commit(); }

    for (int kt = 0; kt < KTILES; ++kt) {
        cp_wait<STAGES - 2>();
        __syncthreads();
        if (kt + STAGES - 1 < KTILES) load_stage((kt + STAGES - 1) % STAGES, kt + STAGES - 1);
        cp_commit();

        uint32_t sa = sbase + (kt % STAGES) * STAGE_B;
        uint32_t sb = sa + A_STAGE_B;
        #pragma unroll
        for (int ks = 0; ks < 2; ++ks) {
            uint32_t fa[4][4];
            #pragma unroll
            for (int mi = 0; mi < 4; mi++) {
                uint32_t addr = sa + (uint32_t)((aRow + mi * 16) * (LDSK * 2)
                                                + (ks * 16 + aK0) * 2);
                asm volatile("ldmatrix.sync.aligned.m8n8.x4.shared.b16 {%0,%1,%2,%3}, [%4];\n"
                    : "=r"(fa[mi][0]), "=r"(fa[mi][1]),
                      "=r"(fa[mi][2]), "=r"(fa[mi][3]) : "r"(addr));
            }
            uint32_t fb[4][4];
            #pragma unroll
            for (int np = 0; np < 4; np++) {
                uint32_t addr = sb + (uint32_t)((bRow + np * 16) * (LDSK * 2)
                                                + (ks * 16 + bK0) * 2);
                asm volatile("ldmatrix.sync.aligned.m8n8.x4.shared.b16 {%0,%1,%2,%3}, [%4];\n"
                    : "=r"(fb[np][0]), "=r"(fb[np][1]),
                      "=r"(fb[np][2]), "=r"(fb[np][3]) : "r"(addr));
            }
            #pragma unroll
            for (int mi = 0; mi < 4; mi++)
                #pragma unroll
                for (int ni = 0; ni < 8; ni++) {
                    uint32_t b0 = fb[ni >> 1][(ni & 1) * 2 + 0];
                    uint32_t b1 = fb[ni >> 1][(ni & 1) * 2 + 1];
                    asm volatile(
                        "mma.sync.aligned.m16n8k16.row.col.f16.f16.f16.f16 "
                        "{%0,%1}, {%2,%3,%4,%5}, {%6,%7}, {%0,%1};\n"
                        : "+r"(acc[mi][ni][0]), "+r"(acc[mi][ni][1])
                        : "r"(fa[mi][0]), "r"(fa[mi][1]),
                          "r"(fa[mi][2]), "r"(fa[mi][3]),
                          "r"(b0), "r"(b1));
                }
        }
    }

    #pragma unroll
    for (int mi = 0; mi < 4; mi++) {
        #pragma unroll
        for (int ni = 0; ni < 8; ni++) {
            int row = bm * 128 + wm * 64 + mi * 16 + (lane >> 2);
            int col = bn * 256 + wn * 64 + ni * 8 + (lane & 3) * 2;
            *(uint32_t*)&g_neg[(size_t)row * QSIZE + col]       = acc[mi][ni][0];
            *(uint32_t*)&g_neg[(size_t)(row + 8) * QSIZE + col] = acc[mi][ni][1];
        }
    }
}

// ---------------------------------------------------------------------------
// k_select with narrow-band histogram (atomics cut ~83%) + full-range fallback.
// ---------------------------------------------------------------------------
#define SEL_T 512
#define NBIN 1024
#define CBUF_CAP 1024
#define SEL_SMEM (QSIZE*2 + NBIN*4 + CBUF_CAP*2)   // 71680 B
#define RLO 0.011f
#define RHI 0.033f
#define RSCALE ((float)NBIN / (RHI - RLO))

__device__ __forceinline__ uint32_t h2ex2(uint32_t x) {
    uint32_t r;
    asm("ex2.approx.f16x2 %0, %1;" : "=r"(r) : "r"(x));
    return r;
}

// Suffix-scan bin finder; also reports in-histogram total.
__device__ __forceinline__ void find_bin(int* hist, int target, int* scs,
                                         int* out_bin, int* out_above,
                                         int* out_total, int tid) {
    int base = tid * 2;
    int c = hist[base] + hist[base + 1];
    scs[tid] = c;
    __syncthreads();
    #pragma unroll
    for (int d = 1; d < SEL_T; d <<= 1) {
        int v = (tid + d < SEL_T) ? scs[tid + d] : 0;
        __syncthreads();
        scs[tid] += v;
        __syncthreads();
    }
    if (tid == 0) *out_total = scs[0];
    int Sincl = scs[tid];
    int Sexcl = (tid + 1 < SEL_T) ? scs[tid + 1] : 0;
    if (Sexcl < target && Sincl >= target) {
        int ca = Sexcl;
        #pragma unroll
        for (int j = 1; j >= 0; --j) {
            int h = hist[base + j];
            if (ca + h >= target) { *out_bin = base + j; *out_above = ca; break; }
            ca += h;
        }
    }
}

__global__ __launch_bounds__(SEL_T, 3) void k_select(const int* __restrict__ ridx) {
    extern __shared__ unsigned char dyn2[];
    __half*  srow  = (__half*)dyn2;                          // 65536 B
    __half2* srow2 = (__half2*)dyn2;
    int*     hist  = (int*)(dyn2 + QSIZE*2);                 // 4096 B
    __half*  cbuf  = (__half*)(dyn2 + QSIZE*2 + NBIN*4);     // 2048 B
    __shared__ int   scs[SEL_T];
    __shared__ float wred[SEL_T/32];
    __shared__ int   s_bin, s_above, s_total, s_nc;
    __shared__ float s_max;

    int b = blockIdx.x, tid = threadIdx.x;

    for (int i = tid; i < NBIN; i += SEL_T) hist[i] = 0;
    if (tid == 0) { s_nc = 0; s_bin = -2; }
    __syncthreads();

    // ---- pass 1: load row, rowmax, narrow-band histogram + high-count
    const uint4* src = (const uint4*)(g_neg + (size_t)b * QSIZE);
    uint4* drow = (uint4*)srow;
    __half2 hm = __floats2half2_rn(-2.0f, -2.0f);
    int cntHi = 0;
    for (int i = tid; i < QSIZE / 8; i += SEL_T) {
        uint4 v = src[i]; drow[i] = v;
        uint32_t ws[4] = {v.x, v.y, v.z, v.w};
        #pragma unroll
        for (int q = 0; q < 4; ++q) {
            __half2 h2 = *(__half2*)&ws[q];
            hm = __hmax2(hm, h2);
            float2 f = __half22float2(h2);
            #pragma unroll
            for (int e = 0; e < 2; ++e) {
                float fv = e ? f.y : f.x;
                if (fv >= RHI) cntHi++;
                else if (fv >= RLO) {
                    int bb = (int)((fv - RLO) * RSCALE);
                    atomicAdd(&hist[min(bb, NBIN - 1)], 1);
                }
            }
        }
    }
    float lmax = fmaxf(__low2float(hm), __high2float(hm));
    #pragma unroll
    for (int o = 16; o; o >>= 1) lmax = fmaxf(lmax, __shfl_xor_sync(0xFFFFFFFFu, lmax, o));
    if ((tid & 31) == 0) wred[tid >> 5] = lmax;
    __syncthreads();
    if (tid == 0) {
        float m = -2.0f;
        for (int w = 0; w < SEL_T/32; ++w) m = fmaxf(m, wred[w]);
        s_max = m;
    }
    // reduce cntHi via scs (suffix-sum)
    scs[tid] = cntHi;
    __syncthreads();
    #pragma unroll
    for (int d = 1; d < SEL_T; d <<= 1) {
        int v = (tid + d < SEL_T) ? scs[tid + d] : 0;
        __syncthreads();
        scs[tid] += v;
        __syncthreads();
    }
    if (tid == 0) s_total = scs[0];          // reuse s_total to pass CHI
    __syncthreads();
    int CHI = s_total;
    float rm = s_max;
    int target = NHARD - CHI;
    __syncthreads();

    find_bin(hist, target, scs, &s_bin, &s_above, &s_total, tid);
    __syncthreads();
    bool fb = (target <= 0) || (target > s_total) || (s_bin < 0);
    int bin1 = s_bin, above = s_above;

    if (fb) {
        // ---- fallback: full-range histogram over [-1,1]
        for (int i = tid; i < NBIN; i += SEL_T) hist[i] = 0;
        if (tid == 0) s_bin = -2;
        __syncthreads();
        for (int i = tid; i < QSIZE; i += SEL_T) {
            float fv = __half2float(srow[i]);
            int bb = (int)((fv + 1.0f) * 512.0f); bb = min(max(bb, 0), NBIN - 1);
            atomicAdd(&hist[bb], 1);
        }
        __syncthreads();
        find_bin(hist, NHARD, scs, &s_bin, &s_above, &s_total, tid);
        __syncthreads();
        bin1 = s_bin; above = s_above; target = NHARD;
    }
    int need = target - above;
    float lo_b  = fb ? ((float)bin1 * (1.0f / 512.0f) - 1.0f)
                     : (RLO + (float)bin1 * (1.0f / RSCALE));
    float subsc = fb ? (512.0f * 1024.0f) : (RSCALE * 1024.0f);
    __syncthreads();

    // ---- pass 2: exp table + masked sum + boundary compaction
    float accx = 0.0f, accy = 0.0f;
    for (int i = tid; i < QSIZE / 2; i += SEL_T) {
        __half2 v2 = srow2[i];
        float2 f = __half22float2(v2);
        bool inc[2], cm[2];
        #pragma unroll
        for (int e = 0; e < 2; ++e) {
            float fv = e ? f.y : f.x;
            if (!fb) {
                if (fv >= RHI) { inc[e] = true; cm[e] = false; }
                else if (fv >= RLO) {
                    int bb = min((int)((fv - RLO) * RSCALE), NBIN - 1);
                    inc[e] = bb > bin1; cm[e] = bb == bin1;
                } else { inc[e] = false; cm[e] = false; }
            } else {
                int bb = (int)((fv + 1.0f) * 512.0f); bb = min(max(bb, 0), NBIN - 1);
                inc[e] = bb > bin1; cm[e] = bb == bin1;
            }
        }
        if (cm[0]) { int p = atomicAdd(&s_nc, 1); if (p < CBUF_CAP) cbuf[p] = __low2half(v2); }
        if (cm[1]) { int p = atomicAdd(&s_nc, 1); if (p < CBUF_CAP) cbuf[p] = __high2half(v2); }
        __half2 xh = __floats2half2_rn((f.x - rm) * KEXP, (f.y - rm) * KEXP);
        uint32_t eu = h2ex2(*(uint32_t*)&xh);
        __half2 e2 = *(__half2*)&eu;
        float2 ef = __half22float2(e2);
        if (inc[0]) accx += ef.x;
        if (inc[1]) accy += ef.y;
        srow2[i] = e2;
    }
    float acc = accx + accy;
    __syncthreads();

    // ---- level 2 on the compacted boundary bin
    int nc = min(s_nc, CBUF_CAP);
    for (int i = tid; i < NBIN; i += SEL_T) hist[i] = 0;
    if (tid == 0) s_bin = -2;
    __syncthreads();
    for (int i = tid; i < nc; i += SEL_T) {
        float s = __half2float(cbuf[i]);
        int sb = (int)((s - lo_b) * subsc); sb = min(max(sb, 0), NBIN - 1);
        atomicAdd(&hist[sb], 1);
    }
    __syncthreads();
    find_bin(hist, need, scs, &s_bin, &s_above, &s_total, tid);
    __syncthreads();
    int sb1 = s_bin, above2 = s_above;
    for (int i = tid; i < nc; i += SEL_T) {
        float s = __half2float(cbuf[i]);
        int sb = (int)((s - lo_b) * subsc); sb = min(max(sb, 0), NBIN - 1);
        if (sb > sb1) acc += __expf((s - rm) * INV_T);
    }
    if (tid == 0) {
        int rem = need - above2;
        float smid = lo_b + ((float)sb1 + 0.5f) / subsc;
        acc += (float)rem * __expf((smid - rm) * INV_T);
    }

    // ---- random-negative gather: pure table lookup
    const int2* ri2 = (const int2*)(ridx + (size_t)b * NRAND);
    for (int i = tid; i < NRAND / 2; i += SEL_T) {
        int2 p = __ldg(ri2 + i);
        acc += __half2float(srow[p.x]) + __half2float(srow[p.y]);
    }

    #pragma unroll
    for (int o = 16; o; o >>= 1) acc += __shfl_xor_sync(0xFFFFFFFFu, acc, o);
    if ((tid & 31) == 0) wred[tid >> 5] = acc;
    __syncthreads();
    if (tid == 0) {
        float tot = 0.0f;
        for (int w = 0; w < SEL_T/32; ++w) tot += wred[w];
        float p_sh = (g_pos[b] - rm) * INV_T;
        tot += __expf(p_sh);
        atomicAdd(&g_sums[0], (double)(logf(tot) - p_sh));
        atomicAdd(&g_sums[1], (g_pos[b] >= rm) ? 1.0 : 0.0);
    }
}

__global__ void k_final(float* out, int n) {
    if (n >= 1) out[0] = (float)(g_sums[0] / (double)BATCH);
    if (n >= 2) out[1] = (float)(g_sums[1] / (double)BATCH);
}

// ---------------------------------------------------------------------------
extern "C" void kernel_launch(void* const* d_in, const int* in_sizes, int n_in,
                              void* d_out, int out_size) {
    const float* eeg   = (const float*)d_in[0];
    const float* clip  = (const float*)d_in[1];
    const float* queue = (const float*)d_in[2];
    const int*   ridx  = (const int*)d_in[3];
    float* out = (float*)d_out;

    cudaFuncSetAttribute(k_gemm,   cudaFuncAttributeMaxDynamicSharedMemorySize, GEMM_SMEM);
    cudaFuncSetAttribute(k_select, cudaFuncAttributeMaxDynamicSharedMemorySize, SEL_SMEM);

    k_zero<<<1, 1>>>();
    k_norm<<<BATCH, 128>>>(eeg, clip);
    k_convq<<<QSIZE * DIM / 4 / 256, 256>>>(queue);
    k_gemm<<<dim3(QSIZE / 256, BATCH / 128), 256, GEMM_SMEM>>>();
    k_select<<<BATCH, SEL_T, SEL_SMEM>>>(ridx);
    k_final<<<1, 1>>>(out, out_size);
}

// round 13
// speedup vs baseline: 1.1738x; 1.1738x over previous
#include <cuda_runtime.h>
#include <cuda_bf16.h>
#include <cuda_fp16.h>
#include <cstdint>
#include <cstddef>

// Problem constants
#define BATCH   4096
#define DIM     512
#define QSIZE   32768
#define NHARD   9830
#define NRAND   22938
#define INV_T   (1.0f/0.07f)
#define KEXP    (INV_T * 1.44269504f)   // log2(e)/T

// -------- device scratch (static allocation; no cudaMalloc allowed) --------
__device__ __half  g_eegn[BATCH * DIM];            // 4 MB  normalized eeg, fp16
__device__ __half  g_qbf[QSIZE * DIM];             // 32 MB queue, fp16
__device__ __half  g_neg[(size_t)BATCH * QSIZE];   // 256 MB
__device__ float   g_pos[BATCH];
__device__ double  g_sums[2];

// ---------------------------------------------------------------------------
__global__ void k_zero() { g_sums[0] = 0.0; g_sums[1] = 0.0; }

__global__ __launch_bounds__(128) void k_norm(const float* __restrict__ eeg,
                                              const float* __restrict__ clip) {
    int b = blockIdx.x, t = threadIdx.x;
    float4 e = ((const float4*)(eeg  + (size_t)b * DIM))[t];
    float4 c = ((const float4*)(clip + (size_t)b * DIM))[t];
    float se = e.x*e.x + e.y*e.y + e.z*e.z + e.w*e.w;
    float sc = c.x*c.x + c.y*c.y + c.z*c.z + c.w*c.w;
    float sd = e.x*c.x + e.y*c.y + e.z*c.z + e.w*c.w;
    #pragma unroll
    for (int o = 16; o; o >>= 1) {
        se += __shfl_down_sync(0xFFFFFFFFu, se, o);
        sc += __shfl_down_sync(0xFFFFFFFFu, sc, o);
        sd += __shfl_down_sync(0xFFFFFFFFu, sd, o);
    }
    __shared__ float rs[3][4];
    __shared__ float sInvE;
    int w = t >> 5, l = t & 31;
    if (l == 0) { rs[0][w] = se; rs[1][w] = sc; rs[2][w] = sd; }
    __syncthreads();
    if (t == 0) {
        float SE = rs[0][0] + rs[0][1] + rs[0][2] + rs[0][3];
        float SC = rs[1][0] + rs[1][1] + rs[1][2] + rs[1][3];
        float SD = rs[2][0] + rs[2][1] + rs[2][2] + rs[2][3];
        float ie = 1.0f / fmaxf(sqrtf(SE), 1e-12f);
        float ic = 1.0f / fmaxf(sqrtf(SC), 1e-12f);
        sInvE = ie;
        g_pos[b] = SD * ie * ic;
    }
    __syncthreads();
    float ie = sInvE;
    __half* dst = g_eegn + (size_t)b * DIM + t * 4;
    dst[0] = __float2half(e.x * ie);
    dst[1] = __float2half(e.y * ie);
    dst[2] = __float2half(e.z * ie);
    dst[3] = __float2half(e.w * ie);
}

__global__ __launch_bounds__(256) void k_convq(const float* __restrict__ q) {
    int i = blockIdx.x * 256 + threadIdx.x;
    float4 v = ((const float4*)q)[i];
    __half2* d = (__half2*)g_qbf;
    d[2 * i]     = __floats2half2_rn(v.x, v.y);
    d[2 * i + 1] = __floats2half2_rn(v.z, v.w);
}

// ---------------------------------------------------------------------------
// mma.sync fp16 GEMM, f16 accumulate. (best measured config, unchanged)
// ---------------------------------------------------------------------------
__device__ __forceinline__ uint32_t smem_u32(const void* p) {
    return (uint32_t)__cvta_generic_to_shared(p);
}
__device__ __forceinline__ void cp16(uint32_t s, const void* g) {
    asm volatile("cp.async.cg.shared.global [%0], [%1], 16;\n" :: "r"(s), "l"(g));
}
__device__ __forceinline__ void cp_commit() { asm volatile("cp.async.commit_group;\n"); }
template <int N> __device__ __forceinline__ void cp_wait() {
    asm volatile("cp.async.wait_group %0;\n" :: "n"(N));
}

#define LDSK 40
#define STAGES 3
#define KTILES 16
#define A_STAGE_B (128 * LDSK * 2)
#define B_STAGE_B (256 * LDSK * 2)
#define STAGE_B   (A_STAGE_B + B_STAGE_B)
#define GEMM_SMEM (STAGES * STAGE_B)   // 92160 B -> 2 CTAs/SM

__global__ __launch_bounds__(256, 2) void k_gemm() {
    extern __shared__ __align__(16) unsigned char smraw[];
    uint32_t sbase = smem_u32(smraw);
    int tid = threadIdx.x, warp = tid >> 5, lane = tid & 31;
    int bn = blockIdx.x, bm = blockIdx.y;
    int wm = warp & 1, wn = warp >> 1;

    const __half* Abase = g_eegn + (size_t)bm * 128 * DIM;
    const __half* Bbase = g_qbf  + (size_t)bn * 256 * DIM;

    auto load_stage = [&](int s, int kt) {
        uint32_t sa = sbase + s * STAGE_B;
        uint32_t sb = sa + A_STAGE_B;
        #pragma unroll
        for (int i = 0; i < 6; ++i) {
            int c = tid + i * 256;
            uint32_t dst; const __half* g; int row, col;
            if (c < 512) { row = c >> 2; col = c & 3; dst = sa;
                           g = Abase + (size_t)row * DIM + kt * 32 + col * 8; }
            else { int cb = c - 512; row = cb >> 2; col = cb & 3; dst = sb;
                   g = Bbase + (size_t)row * DIM + kt * 32 + col * 8; }
            cp16(dst + (uint32_t)(row * (LDSK * 2) + col * 16), g);
        }
    };

    uint32_t acc[4][8][2];
    #pragma unroll
    for (int i = 0; i < 4; i++)
        #pragma unroll
        for (int j = 0; j < 8; j++) { acc[i][j][0] = 0u; acc[i][j][1] = 0u; }

    int aRow = wm * 64 + (lane & 15);
    int aK0  = (lane >> 4) * 8;
    int bRow = wn * 64 + (lane & 7) + ((lane & 16) >> 1);
    int bK0  = ((lane >> 3) & 1) * 8;

    #pragma unroll
    for (int s = 0; s < STAGES - 1; ++s) { load_stage(s, s); cp_commit(); }

    for (int kt = 0; kt < KTILES; ++kt) {
        cp_wait<STAGES - 2>();
        __syncthreads();
        if (kt + STAGES - 1 < KTILES) load_stage((kt + STAGES - 1) % STAGES, kt + STAGES - 1);
        cp_commit();

        uint32_t sa = sbase + (kt % STAGES) * STAGE_B;
        uint32_t sb = sa + A_STAGE_B;
        #pragma unroll
        for (int ks = 0; ks < 2; ++ks) {
            uint32_t fa[4][4];
            #pragma unroll
            for (int mi = 0; mi < 4; mi++) {
                uint32_t addr = sa + (uint32_t)((aRow + mi * 16) * (LDSK * 2)
                                                + (ks * 16 + aK0) * 2);
                asm volatile("ldmatrix.sync.aligned.m8n8.x4.shared.b16 {%0,%1,%2,%3}, [%4];\n"
                    : "=r"(fa[mi][0]), "=r"(fa[mi][1]),
                      "=r"(fa[mi][2]), "=r"(fa[mi][3]) : "r"(addr));
            }
            uint32_t fb[4][4];
            #pragma unroll
            for (int np = 0; np < 4; np++) {
                uint32_t addr = sb + (uint32_t)((bRow + np * 16) * (LDSK * 2)
                                                + (ks * 16 + bK0) * 2);
                asm volatile("ldmatrix.sync.aligned.m8n8.x4.shared.b16 {%0,%1,%2,%3}, [%4];\n"
                    : "=r"(fb[np][0]), "=r"(fb[np][1]),
                      "=r"(fb[np][2]), "=r"(fb[np][3]) : "r"(addr));
            }
            #pragma unroll
            for (int mi = 0; mi < 4; mi++)
                #pragma unroll
                for (int ni = 0; ni < 8; ni++) {
                    uint32_t b0 = fb[ni >> 1][(ni & 1) * 2 + 0];
                    uint32_t b1 = fb[ni >> 1][(ni & 1) * 2 + 1];
                    asm volatile(
                        "mma.sync.aligned.m16n8k16.row.col.f16.f16.f16.f16 "
                        "{%0,%1}, {%2,%3,%4,%5}, {%6,%7}, {%0,%1};\n"
                        : "+r"(acc[mi][ni][0]), "+r"(acc[mi][ni][1])
                        : "r"(fa[mi][0]), "r"(fa[mi][1]),
                          "r"(fa[mi][2]), "r"(fa[mi][3]),
                          "r"(b0), "r"(b1));
                }
        }
    }

    #pragma unroll
    for (int mi = 0; mi < 4; mi++) {
        #pragma unroll
        for (int ni = 0; ni < 8; ni++) {
            int row = bm * 128 + wm * 64 + mi * 16 + (lane >> 2);
            int col = bn * 256 + wn * 64 + ni * 8 + (lane & 3) * 2;
            *(uint32_t*)&g_neg[(size_t)row * QSIZE + col]       = acc[mi][ni][0];
            *(uint32_t*)&g_neg[(size_t)(row + 8) * QSIZE + col] = acc[mi][ni][1];
        }
    }
}

// ---------------------------------------------------------------------------
// k_select v3: minimal-instruction. Narrow-band histogram to locate threshold,
// branch-free half2 SIMD pass2 with self-counted selection + midpoint residual.
// ---------------------------------------------------------------------------
#define SEL_T 512
#define NBIN 1024
#define SEL_SMEM (QSIZE*2 + NBIN*4)    // 69632 B -> 3 CTAs/SM
#define RLO 0.011f
#define RHI 0.033f
#define RSCALE ((float)NBIN / (RHI - RLO))

__device__ __forceinline__ uint32_t h2ex2(uint32_t x) {
    uint32_t r;
    asm("ex2.approx.f16x2 %0, %1;" : "=r"(r) : "r"(x));
    return r;
}

// Suffix-scan bin finder over NBIN bins (2 per thread), warp-shuffle based.
// Writes *s_bin (crossing bin, -1 if none) and *s_total (histogram total).
__device__ __forceinline__ void find_bin3(const int* hist, int target, int* wtot,
                                          int* s_bin, int* s_total, int tid) {
    int lane = tid & 31, w = tid >> 5;
    int base = tid * 2;
    int c = hist[base] + hist[base + 1];
    int s = c;
    #pragma unroll
    for (int o = 1; o < 32; o <<= 1) {
        int t = __shfl_down_sync(0xFFFFFFFFu, s, o);
        if (lane + o < 32) s += t;
    }
    if (lane == 0) wtot[w] = s;          // warp total (bins owned by this warp)
    __syncthreads();                      // also publishes s_bin=-1 init
    int wsuf = 0;
    #pragma unroll
    for (int ww = 0; ww < 16; ++ww) if (ww > w) wsuf += wtot[ww];
    int S_incl = s + wsuf;                // count in bins >= base
    int S_next = S_incl - c;              // count in bins >= base+2
    if (tid == 0) *s_total = S_incl;
    if (S_next < target && S_incl >= target) {
        int h1 = hist[base + 1];
        *s_bin = (S_next + h1 >= target) ? (base + 1) : base;
    }
    __syncthreads();
}

__global__ __launch_bounds__(SEL_T, 3) void k_select(const int* __restrict__ ridx) {
    extern __shared__ unsigned char dyn2[];
    __half*  srow  = (__half*)dyn2;                          // 65536 B
    __half2* srow2 = (__half2*)dyn2;
    int*     hist  = (int*)(dyn2 + QSIZE*2);                 // 4096 B
    __shared__ int   wtotI[16];
    __shared__ float wredF[16];
    __shared__ int   s_bin, s_total, s_chi;
    __shared__ float s_max;

    int b = blockIdx.x, tid = threadIdx.x;
    int lane = tid & 31, w = tid >> 5;

    for (int i = tid; i < NBIN; i += SEL_T) hist[i] = 0;
    if (tid == 0) s_bin = -1;
    __syncthreads();

    // ---- pass 1: load row, rowmax, narrow-band histogram + high-count
    const uint4* src = (const uint4*)(g_neg + (size_t)b * QSIZE);
    uint4* drow = (uint4*)srow;
    __half2 hm = __floats2half2_rn(-2.0f, -2.0f);
    int cntHi = 0;
    #pragma unroll 2
    for (int i = tid; i < QSIZE / 8; i += SEL_T) {
        uint4 v = src[i]; drow[i] = v;
        uint32_t ws[4] = {v.x, v.y, v.z, v.w};
        #pragma unroll
        for (int q = 0; q < 4; ++q) {
            __half2 h2 = *(__half2*)&ws[q];
            hm = __hmax2(hm, h2);
            float2 f = __half22float2(h2);
            if (f.x >= RLO) {
                if (f.x >= RHI) cntHi++;
                else atomicAdd(&hist[min((int)((f.x - RLO) * RSCALE), NBIN - 1)], 1);
            }
            if (f.y >= RLO) {
                if (f.y >= RHI) cntHi++;
                else atomicAdd(&hist[min((int)((f.y - RLO) * RSCALE), NBIN - 1)], 1);
            }
        }
    }
    float lmax = fmaxf(__low2float(hm), __high2float(hm));
    #pragma unroll
    for (int o = 16; o; o >>= 1) {
        lmax = fmaxf(lmax, __shfl_xor_sync(0xFFFFFFFFu, lmax, o));
        cntHi += __shfl_xor_sync(0xFFFFFFFFu, cntHi, o);
    }
    if (lane == 0) { wredF[w] = lmax; wtotI[w] = cntHi; }
    __syncthreads();
    if (tid == 0) {
        float m = -2.0f; int ch = 0;
        for (int ww = 0; ww < 16; ++ww) { m = fmaxf(m, wredF[ww]); ch += wtotI[ww]; }
        s_max = m; s_chi = ch;
    }
    __syncthreads();
    float rm = s_max;
    int target = NHARD - s_chi;

    find_bin3(hist, target, wtotI, &s_bin, &s_total, tid);
    int bin1 = s_bin;
    bool fb = (target <= 0) || (bin1 < 0) || (target > s_total);

    float lo_b, mid;
    if (fb) {
        // rare fallback: full-range histogram over [-1,1]
        __syncthreads();
        for (int i = tid; i < NBIN; i += SEL_T) hist[i] = 0;
        if (tid == 0) s_bin = -1;
        __syncthreads();
        for (int i = tid; i < QSIZE; i += SEL_T) {
            float fv = __half2float(srow[i]);
            int bb = (int)((fv + 1.0f) * 512.0f); bb = min(max(bb, 0), NBIN - 1);
            atomicAdd(&hist[bb], 1);
        }
        __syncthreads();
        find_bin3(hist, NHARD, wtotI, &s_bin, &s_total, tid);
        bin1 = max(s_bin, 0);
        lo_b = -1.0f + (float)bin1 * (1.0f / 512.0f);
        mid  = lo_b + (1.0f / 1024.0f);
    } else {
        lo_b = RLO + (float)bin1 * ((RHI - RLO) / (float)NBIN);
        mid  = lo_b + 0.5f * ((RHI - RLO) / (float)NBIN);
    }

    // ---- pass 2: branch-free SIMD — masked exp-sum, self-counted selection,
    //      overwrite srow with exp table e^((s-rm)/T).
    const __half2 thr2 = __half2half2(__float2half_rd(lo_b));
    const __half2 k2   = __float2half2_rn(KEXP);
    const __half2 c2   = __float2half2_rn(-rm * KEXP);
    float accF = 0.0f;
    __half2 accN = __floats2half2_rn(0.0f, 0.0f);
    #pragma unroll
    for (int g = 0; g < 4; ++g) {
        __half2 accE = __floats2half2_rn(0.0f, 0.0f);
        #pragma unroll
        for (int k = 0; k < 8; ++k) {
            int i = tid + (g * 8 + k) * SEL_T;
            __half2 v2 = srow2[i];
            __half2 m  = __hge2(v2, thr2);
            __half2 xh = __hfma2(v2, k2, c2);
            uint32_t eu = h2ex2(*(uint32_t*)&xh);
            __half2 e2 = *(__half2*)&eu;
            accE = __hfma2(e2, m, accE);
            accN = __hadd2(accN, m);
            srow2[i] = e2;
        }
        accF += __low2float(accE) + __high2float(accE);
    }
    int nsel = (int)__low2float(accN) + (int)__high2float(accN);
    __syncthreads();   // exp table complete before gather

    // ---- random-negative gather: pure table lookup
    const int2* ri2 = (const int2*)(ridx + (size_t)b * NRAND);
    for (int i = tid; i < NRAND / 2; i += SEL_T) {
        int2 p = __ldg(ri2 + i);
        accF += __half2float(srow[p.x]) + __half2float(srow[p.y]);
    }

    // ---- block reduce accF + nsel
    #pragma unroll
    for (int o = 16; o; o >>= 1) {
        accF += __shfl_xor_sync(0xFFFFFFFFu, accF, o);
        nsel += __shfl_xor_sync(0xFFFFFFFFu, nsel, o);
    }
    if (lane == 0) { wredF[w] = accF; wtotI[w] = nsel; }
    __syncthreads();
    if (tid == 0) {
        float tot = 0.0f; int N = 0;
        for (int ww = 0; ww < 16; ++ww) { tot += wredF[ww]; N += wtotI[ww]; }
        float rem = (float)(NHARD - N);
        tot += rem * __expf((mid - rm) * INV_T);
        float p_sh = (g_pos[b] - rm) * INV_T;
        tot += __expf(p_sh);
        atomicAdd(&g_sums[0], (double)(logf(tot) - p_sh));
        atomicAdd(&g_sums[1], (g_pos[b] >= rm) ? 1.0 : 0.0);
    }
}

__global__ void k_final(float* out, int n) {
    if (n >= 1) out[0] = (float)(g_sums[0] / (double)BATCH);
    if (n >= 2) out[1] = (float)(g_sums[1] / (double)BATCH);
}

// ---------------------------------------------------------------------------
extern "C" void kernel_launch(void* const* d_in, const int* in_sizes, int n_in,
                              void* d_out, int out_size) {
    const float* eeg   = (const float*)d_in[0];
    const float* clip  = (const float*)d_in[1];
    const float* queue = (const float*)d_in[2];
    const int*   ridx  = (const int*)d_in[3];
    float* out = (float*)d_out;

    cudaFuncSetAttribute(k_gemm,   cudaFuncAttributeMaxDynamicSharedMemorySize, GEMM_SMEM);
    cudaFuncSetAttribute(k_select, cudaFuncAttributeMaxDynamicSharedMemorySize, SEL_SMEM);

    k_zero<<<1, 1>>>();
    k_norm<<<BATCH, 128>>>(eeg, clip);
    k_convq<<<QSIZE * DIM / 4 / 256, 256>>>(queue);
    k_gemm<<<dim3(QSIZE / 256, BATCH / 128), 256, GEMM_SMEM>>>();
    k_select<<<BATCH, SEL_T, SEL_SMEM>>>(ridx);
    k_final<<<1, 1>>>(out, out_size);
}